// round 15
// baseline (speedup 1.0000x reference)
#include <cuda_runtime.h>
#include <cuda_bf16.h>
#include <mma.h>
#include <cstdint>

using namespace nvcuda;

#define MAX_N 100000
#define N_GRAPHS 64
#define FEAT 64
#define MAX_E 1600000

// ---------------- scratch ----------------
__device__ float g_S[MAX_N * FEAT];
__device__ float g_h[MAX_N * FEAT];
__device__ float g_h2[MAX_N * FEAT];
__device__ int   g_deg[MAX_N];
__device__ int   g_rowstart[MAX_N + 1];
__device__ int   g_cursor[MAX_N];
__device__ int   g_srcs[MAX_E];
__device__ int   g_bsum[128];
__device__ int   g_ei64;
__device__ int   g_b64;

// ---------------- zero degree + dtype detection (merged) ----------------
__global__ void zero_detect_kernel(const void* ei, const void* batch, int nE, int nN) {
    int i = blockIdx.x * blockDim.x + threadIdx.x;
    if (i < nN) g_deg[i] = 0;
    if (blockIdx.x == 0 && threadIdx.x < 32) {
        int lane = threadIdx.x;
        const long long* p = (const long long*)ei;
        long long v = p[lane];
        int ok = (v >= 0 && v < (long long)nN);
        unsigned m = __ballot_sync(0xffffffffu, ok);
        int idx = nN / 2 - 1 - lane;
        long long bv = (idx >= 0) ? ((const long long*)batch)[idx] : 0;
        int bok = (bv >= 0 && bv < 64);
        unsigned bm = __ballot_sync(0xffffffffu, bok);
        if (lane == 0) {
            g_ei64 = (m == 0xffffffffu) ? 1 : 0;
            g_b64  = (bm == 0xffffffffu) ? 1 : 0;
        }
    }
}

// ---------------- CSR build: histogram ----------------
__global__ void hist_kernel(const void* __restrict__ ei_v, int nE) {
    int e = blockIdx.x * blockDim.x + threadIdx.x;
    if (e >= nE) return;
    int dst;
    if (g_ei64) dst = (int)((const long long*)ei_v)[(long long)nE + e];
    else        dst = ((const int*)ei_v)[nE + e];
    atomicAdd(&g_deg[dst], 1);
}

// ---------------- scan phase 1: per-1024-block exclusive scan -------------
__global__ void scan_block_kernel(int nN) {
    __shared__ int wsum[8];
    __shared__ int woff[8];
    int blk = blockIdx.x, t = threadIdx.x;
    int base = blk * 1024 + t * 4;
    int v0 = (base + 0 < nN) ? g_deg[base + 0] : 0;
    int v1 = (base + 1 < nN) ? g_deg[base + 1] : 0;
    int v2 = (base + 2 < nN) ? g_deg[base + 2] : 0;
    int v3 = (base + 3 < nN) ? g_deg[base + 3] : 0;
    int i0 = v0, i1 = i0 + v1, i2 = i1 + v2, i3 = i2 + v3;
    int tot = i3;
    int lane = t & 31, w = t >> 5;
    int sc = tot;
    #pragma unroll
    for (int off = 1; off < 32; off <<= 1) {
        int n = __shfl_up_sync(0xffffffffu, sc, off);
        if (lane >= off) sc += n;
    }
    if (lane == 31) wsum[w] = sc;
    __syncthreads();
    if (t < 8) {
        int v = wsum[t];
        int s = v;
        #pragma unroll
        for (int off = 1; off < 8; off <<= 1) {
            int n = __shfl_up_sync(0xffu, s, off);
            if (t >= off) s += n;
        }
        woff[t] = s - v;
        if (t == 7) g_bsum[blk] = s;
    }
    __syncthreads();
    int excl = woff[w] + (sc - tot);
    if (base + 0 < nN) g_rowstart[base + 0] = excl;
    if (base + 1 < nN) g_rowstart[base + 1] = excl + i0;
    if (base + 2 < nN) g_rowstart[base + 2] = excl + i1;
    if (base + 3 < nN) g_rowstart[base + 3] = excl + i2;
}

// ---------------- scan phase 2 (fused tops): each block re-scans bsums ----
__global__ void scan_add_kernel(int nN, int nE, int nScanBlocks) {
    __shared__ int sboff[128];
    int t = threadIdx.x;
    if (t < 32) {
        int lane = t;
        int v0 = (lane      < nScanBlocks) ? g_bsum[lane]      : 0;
        int v1 = (lane + 32 < nScanBlocks) ? g_bsum[lane + 32] : 0;
        int v2 = (lane + 64 < nScanBlocks) ? g_bsum[lane + 64] : 0;
        int v3 = (lane + 96 < nScanBlocks) ? g_bsum[lane + 96] : 0;
        int s0 = v0, s1 = v1, s2 = v2, s3 = v3;
        #pragma unroll
        for (int off = 1; off < 32; off <<= 1) {
            int n0 = __shfl_up_sync(0xffffffffu, s0, off);
            int n1 = __shfl_up_sync(0xffffffffu, s1, off);
            int n2 = __shfl_up_sync(0xffffffffu, s2, off);
            int n3 = __shfl_up_sync(0xffffffffu, s3, off);
            if (lane >= off) { s0 += n0; s1 += n1; s2 += n2; s3 += n3; }
        }
        int t0 = __shfl_sync(0xffffffffu, s0, 31);
        int t1 = __shfl_sync(0xffffffffu, s1, 31);
        int t2 = __shfl_sync(0xffffffffu, s2, 31);
        sboff[lane]      = s0 - v0;
        sboff[lane + 32] = t0 + (s1 - v1);
        sboff[lane + 64] = t0 + t1 + (s2 - v2);
        sboff[lane + 96] = t0 + t1 + t2 + (s3 - v3);
    }
    __syncthreads();
    int i = blockIdx.x * blockDim.x + t;
    if (i < nN) {
        int s = g_rowstart[i] + sboff[i >> 10];
        g_rowstart[i] = s;
        g_cursor[i] = s;
    }
    if (i == 0) g_rowstart[nN] = nE;
}

// ---------------- CSR build: placement ----------------
__global__ void fill_kernel(const void* __restrict__ ei_v, int nE) {
    int e = blockIdx.x * blockDim.x + threadIdx.x;
    if (e >= nE) return;
    int src, dst;
    if (g_ei64) {
        const long long* ei = (const long long*)ei_v;
        src = (int)ei[e];
        dst = (int)ei[(long long)nE + e];
    } else {
        const int* ei = (const int*)ei_v;
        src = ei[e];
        dst = ei[nE + e];
    }
    int pos = atomicAdd(&g_cursor[dst], 1);
    g_srcs[pos] = src;
}

// ---------------- gather-mean (node-range chunk) ----------------
__global__ void gather_kernel(const float* __restrict__ x, int nodeBase, int nodeEnd,
                              int fromH) {
    int gtid = blockIdx.x * blockDim.x + threadIdx.x;
    int node = nodeBase + (gtid >> 5);
    int lane = gtid & 31;
    if (node >= nodeEnd) return;
    const float* base = fromH ? (const float*)g_h : x;
    int s = g_rowstart[node];
    int e = g_rowstart[node + 1];
    float ax = 0.f, ay = 0.f;

    for (int b = s; b < e; b += 32) {
        int cnt = min(32, e - b);
        int idxv = (lane < cnt) ? __ldg(&g_srcs[b + lane]) : 0;
        int j = 0;
        for (; j + 4 <= cnt; j += 4) {
            int a0 = __shfl_sync(0xffffffffu, idxv, j);
            int a1 = __shfl_sync(0xffffffffu, idxv, j + 1);
            int a2 = __shfl_sync(0xffffffffu, idxv, j + 2);
            int a3 = __shfl_sync(0xffffffffu, idxv, j + 3);
            float2 v0 = __ldg((const float2*)(base + (size_t)a0 * FEAT) + lane);
            float2 v1 = __ldg((const float2*)(base + (size_t)a1 * FEAT) + lane);
            float2 v2 = __ldg((const float2*)(base + (size_t)a2 * FEAT) + lane);
            float2 v3 = __ldg((const float2*)(base + (size_t)a3 * FEAT) + lane);
            ax += (v0.x + v1.x) + (v2.x + v3.x);
            ay += (v0.y + v1.y) + (v2.y + v3.y);
        }
        for (; j < cnt; j++) {
            int a0 = __shfl_sync(0xffffffffu, idxv, j);
            float2 v0 = __ldg((const float2*)(base + (size_t)a0 * FEAT) + lane);
            ax += v0.x; ay += v0.y;
        }
    }
    float inv = 1.0f / fmaxf((float)(e - s), 1.0f);
    reinterpret_cast<float2*>(g_S)[node * 32 + lane] = make_float2(ax * inv, ay * inv);
}

// ---------------- wmma tf32 fused layer GEMM (row-range chunk) ------------
#define A_LDF 136
#define B_LDF 68
__global__ void __launch_bounds__(256, 2)
mma_layer(const float* __restrict__ Xin,
          const float* __restrict__ Wrel,
          const float* __restrict__ Wroot,
          const float* __restrict__ bias,
          float* __restrict__ out,
          int rowOffset, int nRows) {
    extern __shared__ float dynf[];
    float* sA = dynf;                  // 128*136*4 = 69632B
    float* sB = dynf + 128 * A_LDF;    // 128*68*4  = 34816B
    float* stage = dynf;               // reused post-compute
    __shared__ float s_bias[64];

    int tid = threadIdx.x;
    int warp = tid >> 5;
    int rowBase = rowOffset + blockIdx.x * 128;

    if (tid < 64) s_bias[tid] = bias[tid];

    for (int i = tid; i < 128 * 64; i += 256) {
        int k = i >> 6, n = i & 63;
        float w = (k < 64) ? Wrel[k * 64 + n] : Wroot[(k - 64) * 64 + n];
        sB[k * B_LDF + n] = wmma::__float_to_tf32(w);
    }

    for (int i = tid; i < 128 * 64; i += 256) {
        int r = i >> 6, k = i & 63;
        int grow = rowBase + r;
        float vS = 0.f, vX = 0.f;
        if (grow < nRows) {
            vS = g_S[(size_t)grow * 64 + k];
            vX = Xin[(size_t)grow * 64 + k];
        }
        sA[r * A_LDF + k]      = wmma::__float_to_tf32(vS);
        sA[r * A_LDF + 64 + k] = wmma::__float_to_tf32(vX);
    }
    __syncthreads();

    wmma::fragment<wmma::accumulator, 16, 16, 8, float> acc[4];
    #pragma unroll
    for (int j = 0; j < 4; j++) wmma::fill_fragment(acc[j], 0.0f);

    #pragma unroll
    for (int ks = 0; ks < 16; ks++) {
        wmma::fragment<wmma::matrix_a, 16, 16, 8, wmma::precision::tf32, wmma::row_major> aF;
        wmma::load_matrix_sync(aF, sA + (warp * 16) * A_LDF + ks * 8, A_LDF);
        #pragma unroll
        for (int j = 0; j < 4; j++) {
            wmma::fragment<wmma::matrix_b, 16, 16, 8, wmma::precision::tf32, wmma::row_major> bF;
            wmma::load_matrix_sync(bF, sB + (ks * 8) * B_LDF + j * 16, B_LDF);
            wmma::mma_sync(acc[j], aF, bF, acc[j]);
        }
    }
    __syncthreads();

    #pragma unroll
    for (int j = 0; j < 4; j++)
        wmma::store_matrix_sync(stage + (warp * 16) * 68 + j * 16, acc[j], 68,
                                wmma::mem_row_major);
    __syncthreads();

    for (int i = tid; i < 128 * 64; i += 256) {
        int r = i >> 6, c = i & 63;
        int grow = rowBase + r;
        if (grow < nRows) {
            float v = stage[r * 68 + c] + s_bias[c];
            out[(size_t)grow * 64 + c] = fmaxf(v, 0.f);
        }
    }
}

// ---------------- head with fused pooling: one block per graph ------------
__device__ __forceinline__ long long batch_at(const void* b, int i, int is64) {
    return is64 ? ((const long long*)b)[i] : (long long)((const int*)b)[i];
}

__global__ void head_pool_kernel(const void* __restrict__ batch, int nRows,
                                 const float* __restrict__ Wh, const float* __restrict__ bh,
                                 const float* __restrict__ Wc, const float* __restrict__ bc,
                                 const float* __restrict__ Wo, const float* __restrict__ bo,
                                 float* __restrict__ out) {
    int g = blockIdx.x;
    int is64 = g_b64;
    int lo = 0, hi = nRows;
    while (lo < hi) { int m = (lo + hi) >> 1; if (batch_at(batch, m, is64) < g) lo = m + 1; else hi = m; }
    int start = lo;
    lo = 0; hi = nRows;
    while (lo < hi) { int m = (lo + hi) >> 1; if (batch_at(batch, m, is64) < g + 1) lo = m + 1; else hi = m; }
    int end = lo;

    int tid = threadIdx.x;
    int feat = tid & 63;
    int rl   = tid >> 6;

    __shared__ float sm[4][64];
    __shared__ float sp[64];
    __shared__ float sh[64];

    float s = 0.f;
    for (int r = start + rl; r < end; r += 4)
        s += g_h2[(long long)r * FEAT + feat];
    sm[rl][feat] = s;
    __syncthreads();
    if (rl == 0) {
        float tot = sm[0][feat] + sm[1][feat] + sm[2][feat] + sm[3][feat];
        sp[feat] = tot / fmaxf((float)(end - start), 1.0f);
    }
    __syncthreads();

    if (tid < 64) {
        int j = tid;
        float ah = bh[j], ac = bc[j];
        #pragma unroll 8
        for (int k = 0; k < 64; k++) {
            float p = sp[k];
            ah += p * Wh[k * 64 + j];
            ac += p * Wc[k * 64 + j];
        }
        sh[j] = ah;
        out[2048 + g * 64 + j] = ah;
        out[2048 + 4096 + g * 64 + j] = ac;
    }
    __syncthreads();

    if (tid < 32) {
        int lane = tid;
        float z = bo[lane];
        #pragma unroll 8
        for (int k = 0; k < 64; k++)
            z += sh[k] * Wo[k * 32 + lane];
        float m = z;
        #pragma unroll
        for (int off = 16; off > 0; off >>= 1)
            m = fmaxf(m, __shfl_xor_sync(0xffffffffu, m, off));
        float e = expf(z - m);
        #pragma unroll
        for (int off = 16; off > 0; off >>= 1)
            e += __shfl_xor_sync(0xffffffffu, e, off);
        out[g * 32 + lane] = z - m - logf(e);
    }
}

// ---------------- launch (fork-join overlap: gatherB ∥ gemmA) -------------
extern "C" void kernel_launch(void* const* d_in, const int* in_sizes, int n_in,
                              void* d_out, int out_size) {
    const float* x     = (const float*)d_in[0];
    const void*  ei    = d_in[1];
    const void*  batch = d_in[2];
    const float* W1    = (const float*)d_in[3];
    const float* root1 = (const float*)d_in[4];
    const float* b1    = (const float*)d_in[5];
    const float* W2    = (const float*)d_in[6];
    const float* root2 = (const float*)d_in[7];
    const float* b2    = (const float*)d_in[8];
    const float* Wh    = (const float*)d_in[9];
    const float* bh    = (const float*)d_in[10];
    const float* Wc    = (const float*)d_in[11];
    const float* bc    = (const float*)d_in[12];
    const float* Wo    = (const float*)d_in[13];
    const float* bo    = (const float*)d_in[14];

    int nN = in_sizes[0] / FEAT;   // 100000
    int nE = in_sizes[1] / 2;      // 1600000

    int eBlocks = (nE + 255) / 256;
    int nBlocks = (nN + 255) / 256;
    int scanBlocks = (nN + 1023) / 1024;
    size_t dynBytes = (size_t)(128 * A_LDF + 128 * B_LDF) * 4;

    // chunk split: A = [0, half), B = [half, nN); half multiple of 128
    int half = ((nN / 2) + 127) & ~127;
    int gBlkA = (half * 32 + 255) / 256;
    int gBlkB = ((nN - half) * 32 + 255) / 256;
    int mBlkA = half / 128;
    int mBlkB = (nN - half + 127) / 128;

    float* h1 = nullptr; float* h2 = nullptr;
    cudaGetSymbolAddress((void**)&h1, g_h);
    cudaGetSymbolAddress((void**)&h2, g_h2);

    cudaFuncSetAttribute(mma_layer, cudaFuncAttributeMaxDynamicSharedMemorySize,
                         (int)dynBytes);

    // persistent side stream + events (created once, on the uncaptured
    // correctness call; only record/wait are captured — identical per call)
    static cudaStream_t s2 = []() {
        cudaStream_t s; cudaStreamCreateWithFlags(&s, cudaStreamNonBlocking); return s;
    }();
    static cudaEvent_t evF1 = []() {
        cudaEvent_t e; cudaEventCreateWithFlags(&e, cudaEventDisableTiming); return e;
    }();
    static cudaEvent_t evJ1 = []() {
        cudaEvent_t e; cudaEventCreateWithFlags(&e, cudaEventDisableTiming); return e;
    }();
    static cudaEvent_t evF2 = []() {
        cudaEvent_t e; cudaEventCreateWithFlags(&e, cudaEventDisableTiming); return e;
    }();
    static cudaEvent_t evJ2 = []() {
        cudaEvent_t e; cudaEventCreateWithFlags(&e, cudaEventDisableTiming); return e;
    }();

    // ---- CSR build (legacy stream) ----
    zero_detect_kernel<<<nBlocks, 256>>>(ei, batch, nE, nN);
    hist_kernel<<<eBlocks, 256>>>(ei, nE);
    scan_block_kernel<<<scanBlocks, 256>>>(nN);
    scan_add_kernel<<<nBlocks, 256>>>(nN, nE, scanBlocks);
    fill_kernel<<<eBlocks, 256>>>(ei, nE);

    // ---- layer 1: gatherA -> { gatherB (s2) || gemmA } -> gemmB ----
    gather_kernel<<<gBlkA, 256>>>(x, 0, half, 0);
    cudaEventRecord(evF1, 0);
    cudaStreamWaitEvent(s2, evF1, 0);
    gather_kernel<<<gBlkB, 256, 0, s2>>>(x, half, nN, 0);
    mma_layer<<<mBlkA, 256, dynBytes>>>(x, W1, root1, b1, h1, 0, nN);
    cudaEventRecord(evJ1, s2);
    cudaStreamWaitEvent(0, evJ1, 0);
    mma_layer<<<mBlkB, 256, dynBytes>>>(x, W1, root1, b1, h1, half, nN);

    // ---- layer 2: same pattern (gather2 needs ALL of h1 — stream order ok)
    gather_kernel<<<gBlkA, 256>>>(x, 0, half, 1);
    cudaEventRecord(evF2, 0);
    cudaStreamWaitEvent(s2, evF2, 0);
    gather_kernel<<<gBlkB, 256, 0, s2>>>(x, half, nN, 1);
    mma_layer<<<mBlkA, 256, dynBytes>>>(h1, W2, root2, b2, h2, 0, nN);
    cudaEventRecord(evJ2, s2);
    cudaStreamWaitEvent(0, evJ2, 0);
    mma_layer<<<mBlkB, 256, dynBytes>>>(h1, W2, root2, b2, h2, half, nN);

    // ---- pool + heads (fused) ----
    head_pool_kernel<<<N_GRAPHS, 256>>>(batch, nN, Wh, bh, Wc, bc, Wo, bo,
                                        (float*)d_out);
}

// round 16
// speedup vs baseline: 1.4816x; 1.4816x over previous
#include <cuda_runtime.h>
#include <cuda_bf16.h>
#include <mma.h>
#include <cstdint>

using namespace nvcuda;

#define MAX_N 100000
#define N_GRAPHS 64
#define FEAT 64
#define MAX_E 1600000

// ---------------- scratch ----------------
__device__ float g_S[MAX_N * FEAT];
__device__ float g_h[MAX_N * FEAT];
__device__ float g_h2[MAX_N * FEAT];
__device__ int   g_deg[MAX_N];
__device__ int   g_rowstart[MAX_N + 1];
__device__ int   g_cursor[MAX_N];
__device__ int   g_srcs[MAX_E];
__device__ int   g_bsum[128];
__device__ int   g_ei64;
__device__ int   g_b64;

// ---------------- zero degree + dtype detection (merged) ----------------
__global__ void zero_detect_kernel(const void* ei, const void* batch, int nE, int nN) {
    int i = blockIdx.x * blockDim.x + threadIdx.x;
    if (i < nN) g_deg[i] = 0;
    if (blockIdx.x == 0 && threadIdx.x < 32) {
        int lane = threadIdx.x;
        const long long* p = (const long long*)ei;
        long long v = p[lane];
        int ok = (v >= 0 && v < (long long)nN);
        unsigned m = __ballot_sync(0xffffffffu, ok);
        int idx = nN / 2 - 1 - lane;
        long long bv = (idx >= 0) ? ((const long long*)batch)[idx] : 0;
        int bok = (bv >= 0 && bv < 64);
        unsigned bm = __ballot_sync(0xffffffffu, bok);
        if (lane == 0) {
            g_ei64 = (m == 0xffffffffu) ? 1 : 0;
            g_b64  = (bm == 0xffffffffu) ? 1 : 0;
        }
    }
}

// ---------------- CSR build: histogram (2 edges/thread, vector loads) -----
__global__ void hist_kernel(const void* __restrict__ ei_v, int nE) {
    int e = (blockIdx.x * blockDim.x + threadIdx.x) * 2;
    if (e >= nE) return;
    int d0, d1 = -1;
    if (g_ei64) {
        const long long* ei = (const long long*)ei_v;
        if (e + 1 < nE) {
            longlong2 dd = *reinterpret_cast<const longlong2*>(ei + (long long)nE + e);
            d0 = (int)dd.x; d1 = (int)dd.y;
        } else {
            d0 = (int)ei[(long long)nE + e];
        }
    } else {
        const int* ei = (const int*)ei_v;
        if (e + 1 < nE) {
            int2 dd = *reinterpret_cast<const int2*>(ei + nE + e);
            d0 = dd.x; d1 = dd.y;
        } else {
            d0 = ei[nE + e];
        }
    }
    atomicAdd(&g_deg[d0], 1);
    if (d1 >= 0) atomicAdd(&g_deg[d1], 1);
}

// ---------------- scan phase 1: per-1024-block exclusive scan -------------
__global__ void scan_block_kernel(int nN) {
    __shared__ int wsum[8];
    __shared__ int woff[8];
    int blk = blockIdx.x, t = threadIdx.x;
    int base = blk * 1024 + t * 4;
    int v0 = (base + 0 < nN) ? g_deg[base + 0] : 0;
    int v1 = (base + 1 < nN) ? g_deg[base + 1] : 0;
    int v2 = (base + 2 < nN) ? g_deg[base + 2] : 0;
    int v3 = (base + 3 < nN) ? g_deg[base + 3] : 0;
    int i0 = v0, i1 = i0 + v1, i2 = i1 + v2, i3 = i2 + v3;
    int tot = i3;
    int lane = t & 31, w = t >> 5;
    int sc = tot;
    #pragma unroll
    for (int off = 1; off < 32; off <<= 1) {
        int n = __shfl_up_sync(0xffffffffu, sc, off);
        if (lane >= off) sc += n;
    }
    if (lane == 31) wsum[w] = sc;
    __syncthreads();
    if (t < 8) {
        int v = wsum[t];
        int s = v;
        #pragma unroll
        for (int off = 1; off < 8; off <<= 1) {
            int n = __shfl_up_sync(0xffu, s, off);
            if (t >= off) s += n;
        }
        woff[t] = s - v;
        if (t == 7) g_bsum[blk] = s;
    }
    __syncthreads();
    int excl = woff[w] + (sc - tot);
    if (base + 0 < nN) g_rowstart[base + 0] = excl;
    if (base + 1 < nN) g_rowstart[base + 1] = excl + i0;
    if (base + 2 < nN) g_rowstart[base + 2] = excl + i1;
    if (base + 3 < nN) g_rowstart[base + 3] = excl + i2;
}

// ---------------- scan phase 2 (fused tops): each block re-scans bsums ----
__global__ void scan_add_kernel(int nN, int nE, int nScanBlocks) {
    __shared__ int sboff[128];
    int t = threadIdx.x;
    if (t < 32) {
        int lane = t;
        int v0 = (lane      < nScanBlocks) ? g_bsum[lane]      : 0;
        int v1 = (lane + 32 < nScanBlocks) ? g_bsum[lane + 32] : 0;
        int v2 = (lane + 64 < nScanBlocks) ? g_bsum[lane + 64] : 0;
        int v3 = (lane + 96 < nScanBlocks) ? g_bsum[lane + 96] : 0;
        int s0 = v0, s1 = v1, s2 = v2, s3 = v3;
        #pragma unroll
        for (int off = 1; off < 32; off <<= 1) {
            int n0 = __shfl_up_sync(0xffffffffu, s0, off);
            int n1 = __shfl_up_sync(0xffffffffu, s1, off);
            int n2 = __shfl_up_sync(0xffffffffu, s2, off);
            int n3 = __shfl_up_sync(0xffffffffu, s3, off);
            if (lane >= off) { s0 += n0; s1 += n1; s2 += n2; s3 += n3; }
        }
        int t0 = __shfl_sync(0xffffffffu, s0, 31);
        int t1 = __shfl_sync(0xffffffffu, s1, 31);
        int t2 = __shfl_sync(0xffffffffu, s2, 31);
        sboff[lane]      = s0 - v0;
        sboff[lane + 32] = t0 + (s1 - v1);
        sboff[lane + 64] = t0 + t1 + (s2 - v2);
        sboff[lane + 96] = t0 + t1 + t2 + (s3 - v3);
    }
    __syncthreads();
    int i = blockIdx.x * blockDim.x + t;
    if (i < nN) {
        int s = g_rowstart[i] + sboff[i >> 10];
        g_rowstart[i] = s;
        g_cursor[i] = s;
    }
    if (i == 0) g_rowstart[nN] = nE;
}

// ---------------- CSR build: placement (2 edges/thread) -------------------
__global__ void fill_kernel(const void* __restrict__ ei_v, int nE) {
    int e = (blockIdx.x * blockDim.x + threadIdx.x) * 2;
    if (e >= nE) return;
    int s0, d0, s1 = -1, d1 = -1;
    if (g_ei64) {
        const long long* ei = (const long long*)ei_v;
        if (e + 1 < nE) {
            longlong2 ss = *reinterpret_cast<const longlong2*>(ei + e);
            longlong2 dd = *reinterpret_cast<const longlong2*>(ei + (long long)nE + e);
            s0 = (int)ss.x; s1 = (int)ss.y;
            d0 = (int)dd.x; d1 = (int)dd.y;
        } else {
            s0 = (int)ei[e];
            d0 = (int)ei[(long long)nE + e];
        }
    } else {
        const int* ei = (const int*)ei_v;
        if (e + 1 < nE) {
            int2 ss = *reinterpret_cast<const int2*>(ei + e);
            int2 dd = *reinterpret_cast<const int2*>(ei + nE + e);
            s0 = ss.x; s1 = ss.y;
            d0 = dd.x; d1 = dd.y;
        } else {
            s0 = ei[e];
            d0 = ei[nE + e];
        }
    }
    int p0 = atomicAdd(&g_cursor[d0], 1);
    g_srcs[p0] = s0;
    if (d1 >= 0) {
        int p1 = atomicAdd(&g_cursor[d1], 1);
        g_srcs[p1] = s1;
    }
}

// ---------------- gather-mean (R7 fp32 form — proven wall, keep) ----------
__global__ void gather_kernel(const float* __restrict__ x, int nN, int fromH) {
    int gtid = blockIdx.x * blockDim.x + threadIdx.x;
    int node = gtid >> 5;
    int lane = gtid & 31;
    if (node >= nN) return;
    const float* base = fromH ? (const float*)g_h : x;
    int s = g_rowstart[node];
    int e = g_rowstart[node + 1];
    float ax = 0.f, ay = 0.f;

    for (int b = s; b < e; b += 32) {
        int cnt = min(32, e - b);
        int idxv = (lane < cnt) ? __ldg(&g_srcs[b + lane]) : 0;
        int j = 0;
        for (; j + 4 <= cnt; j += 4) {
            int a0 = __shfl_sync(0xffffffffu, idxv, j);
            int a1 = __shfl_sync(0xffffffffu, idxv, j + 1);
            int a2 = __shfl_sync(0xffffffffu, idxv, j + 2);
            int a3 = __shfl_sync(0xffffffffu, idxv, j + 3);
            float2 v0 = __ldg((const float2*)(base + (size_t)a0 * FEAT) + lane);
            float2 v1 = __ldg((const float2*)(base + (size_t)a1 * FEAT) + lane);
            float2 v2 = __ldg((const float2*)(base + (size_t)a2 * FEAT) + lane);
            float2 v3 = __ldg((const float2*)(base + (size_t)a3 * FEAT) + lane);
            ax += (v0.x + v1.x) + (v2.x + v3.x);
            ay += (v0.y + v1.y) + (v2.y + v3.y);
        }
        for (; j < cnt; j++) {
            int a0 = __shfl_sync(0xffffffffu, idxv, j);
            float2 v0 = __ldg((const float2*)(base + (size_t)a0 * FEAT) + lane);
            ax += v0.x; ay += v0.y;
        }
    }
    float inv = 1.0f / fmaxf((float)(e - s), 1.0f);
    reinterpret_cast<float2*>(g_S)[node * 32 + lane] = make_float2(ax * inv, ay * inv);
}

// ---------------- wmma tf32 fused layer GEMM (R14/R11 form, occ=2) --------
#define A_LDF 136
#define B_LDF 68
__global__ void __launch_bounds__(256, 2)
mma_layer(const float* __restrict__ Xin,
          const float* __restrict__ Wrel,
          const float* __restrict__ Wroot,
          const float* __restrict__ bias,
          float* __restrict__ out,
          int nRows) {
    extern __shared__ float dynf[];
    float* sA = dynf;                  // 128*136*4 = 69632B
    float* sB = dynf + 128 * A_LDF;    // 128*68*4  = 34816B
    float* stage = dynf;               // reused post-compute
    __shared__ float s_bias[64];

    int tid = threadIdx.x;
    int warp = tid >> 5;
    int rowBase = blockIdx.x * 128;

    if (tid < 64) s_bias[tid] = bias[tid];

    for (int i = tid; i < 128 * 64; i += 256) {
        int k = i >> 6, n = i & 63;
        float w = (k < 64) ? Wrel[k * 64 + n] : Wroot[(k - 64) * 64 + n];
        sB[k * B_LDF + n] = wmma::__float_to_tf32(w);
    }

    for (int i = tid; i < 128 * 64; i += 256) {
        int r = i >> 6, k = i & 63;
        int grow = rowBase + r;
        float vS = 0.f, vX = 0.f;
        if (grow < nRows) {
            vS = g_S[(size_t)grow * 64 + k];
            vX = Xin[(size_t)grow * 64 + k];
        }
        sA[r * A_LDF + k]      = wmma::__float_to_tf32(vS);
        sA[r * A_LDF + 64 + k] = wmma::__float_to_tf32(vX);
    }
    __syncthreads();

    wmma::fragment<wmma::accumulator, 16, 16, 8, float> acc[4];
    #pragma unroll
    for (int j = 0; j < 4; j++) wmma::fill_fragment(acc[j], 0.0f);

    #pragma unroll
    for (int ks = 0; ks < 16; ks++) {
        wmma::fragment<wmma::matrix_a, 16, 16, 8, wmma::precision::tf32, wmma::row_major> aF;
        wmma::load_matrix_sync(aF, sA + (warp * 16) * A_LDF + ks * 8, A_LDF);
        #pragma unroll
        for (int j = 0; j < 4; j++) {
            wmma::fragment<wmma::matrix_b, 16, 16, 8, wmma::precision::tf32, wmma::row_major> bF;
            wmma::load_matrix_sync(bF, sB + (ks * 8) * B_LDF + j * 16, B_LDF);
            wmma::mma_sync(acc[j], aF, bF, acc[j]);
        }
    }
    __syncthreads();

    #pragma unroll
    for (int j = 0; j < 4; j++)
        wmma::store_matrix_sync(stage + (warp * 16) * 68 + j * 16, acc[j], 68,
                                wmma::mem_row_major);
    __syncthreads();

    for (int i = tid; i < 128 * 64; i += 256) {
        int r = i >> 6, c = i & 63;
        int grow = rowBase + r;
        if (grow < nRows) {
            float v = stage[r * 68 + c] + s_bias[c];
            out[(size_t)grow * 64 + c] = fmaxf(v, 0.f);
        }
    }
}

// ---------------- head with fused pooling: one block per graph ------------
__device__ __forceinline__ long long batch_at(const void* b, int i, int is64) {
    return is64 ? ((const long long*)b)[i] : (long long)((const int*)b)[i];
}

__global__ void head_pool_kernel(const void* __restrict__ batch, int nRows,
                                 const float* __restrict__ Wh, const float* __restrict__ bh,
                                 const float* __restrict__ Wc, const float* __restrict__ bc,
                                 const float* __restrict__ Wo, const float* __restrict__ bo,
                                 float* __restrict__ out) {
    int g = blockIdx.x;
    int is64 = g_b64;
    int lo = 0, hi = nRows;
    while (lo < hi) { int m = (lo + hi) >> 1; if (batch_at(batch, m, is64) < g) lo = m + 1; else hi = m; }
    int start = lo;
    lo = 0; hi = nRows;
    while (lo < hi) { int m = (lo + hi) >> 1; if (batch_at(batch, m, is64) < g + 1) lo = m + 1; else hi = m; }
    int end = lo;

    int tid = threadIdx.x;
    int feat = tid & 63;
    int rl   = tid >> 6;

    __shared__ float sm[4][64];
    __shared__ float sp[64];
    __shared__ float sh[64];

    float s = 0.f;
    for (int r = start + rl; r < end; r += 4)
        s += g_h2[(long long)r * FEAT + feat];
    sm[rl][feat] = s;
    __syncthreads();
    if (rl == 0) {
        float tot = sm[0][feat] + sm[1][feat] + sm[2][feat] + sm[3][feat];
        sp[feat] = tot / fmaxf((float)(end - start), 1.0f);
    }
    __syncthreads();

    if (tid < 64) {
        int j = tid;
        float ah = bh[j], ac = bc[j];
        #pragma unroll 8
        for (int k = 0; k < 64; k++) {
            float p = sp[k];
            ah += p * Wh[k * 64 + j];
            ac += p * Wc[k * 64 + j];
        }
        sh[j] = ah;
        out[2048 + g * 64 + j] = ah;
        out[2048 + 4096 + g * 64 + j] = ac;
    }
    __syncthreads();

    if (tid < 32) {
        int lane = tid;
        float z = bo[lane];
        #pragma unroll 8
        for (int k = 0; k < 64; k++)
            z += sh[k] * Wo[k * 32 + lane];
        float m = z;
        #pragma unroll
        for (int off = 16; off > 0; off >>= 1)
            m = fmaxf(m, __shfl_xor_sync(0xffffffffu, m, off));
        float e = expf(z - m);
        #pragma unroll
        for (int off = 16; off > 0; off >>= 1)
            e += __shfl_xor_sync(0xffffffffu, e, off);
        out[g * 32 + lane] = z - m - logf(e);
    }
}

// ---------------- launch (single stream, R14 structure) -------------------
extern "C" void kernel_launch(void* const* d_in, const int* in_sizes, int n_in,
                              void* d_out, int out_size) {
    const float* x     = (const float*)d_in[0];
    const void*  ei    = d_in[1];
    const void*  batch = d_in[2];
    const float* W1    = (const float*)d_in[3];
    const float* root1 = (const float*)d_in[4];
    const float* b1    = (const float*)d_in[5];
    const float* W2    = (const float*)d_in[6];
    const float* root2 = (const float*)d_in[7];
    const float* b2    = (const float*)d_in[8];
    const float* Wh    = (const float*)d_in[9];
    const float* bh    = (const float*)d_in[10];
    const float* Wc    = (const float*)d_in[11];
    const float* bc    = (const float*)d_in[12];
    const float* Wo    = (const float*)d_in[13];
    const float* bo    = (const float*)d_in[14];

    int nN = in_sizes[0] / FEAT;   // 100000
    int nE = in_sizes[1] / 2;      // 1600000

    int e2Blocks = ((nE + 1) / 2 + 255) / 256;
    int nBlocks = (nN + 255) / 256;
    int scanBlocks = (nN + 1023) / 1024;      // <=128
    int gatherBlocks = (nN * 32 + 255) / 256;
    int mmaBlocks = (nN + 127) / 128;
    size_t dynBytes = (size_t)(128 * A_LDF + 128 * B_LDF) * 4;   // 104448B

    float* h1 = nullptr; float* h2 = nullptr;
    cudaGetSymbolAddress((void**)&h1, g_h);
    cudaGetSymbolAddress((void**)&h2, g_h2);

    cudaFuncSetAttribute(mma_layer, cudaFuncAttributeMaxDynamicSharedMemorySize,
                         (int)dynBytes);

    // CSR build
    zero_detect_kernel<<<nBlocks, 256>>>(ei, batch, nE, nN);
    hist_kernel<<<e2Blocks, 256>>>(ei, nE);
    scan_block_kernel<<<scanBlocks, 256>>>(nN);
    scan_add_kernel<<<nBlocks, 256>>>(nN, nE, scanBlocks);
    fill_kernel<<<e2Blocks, 256>>>(ei, nE);

    // layer 1
    gather_kernel<<<gatherBlocks, 256>>>(x, nN, 0);
    mma_layer<<<mmaBlocks, 256, dynBytes>>>(x, W1, root1, b1, h1, nN);

    // layer 2
    gather_kernel<<<gatherBlocks, 256>>>(x, nN, 1);
    mma_layer<<<mmaBlocks, 256, dynBytes>>>(h1, W2, root2, b2, h2, nN);

    // pool + heads (fused)
    head_pool_kernel<<<N_GRAPHS, 256>>>(batch, nN, Wh, bh, Wc, bc, Wo, bo,
                                        (float*)d_out);
}